// round 5
// baseline (speedup 1.0000x reference)
#include <cuda_runtime.h>

#define NP      16384
#define NTOT    (2 * NP)
#define G       64
#define C1      (G * G * G)            // 262144 cells per cloud
#define C2      (2 * C1)               // 524288
#define GRID_LO (-4.8f)
#define H       0.15f
#define INV_H   (1.0f / 0.15f)
#define SCALE   1099511627776.0        // 2^40

typedef unsigned long long ull;

// ---------------- scratch (device globals; zero-initialized at load) -------
__device__ int    g_counts[C2];        // invariant: zero at kernel_launch entry
__device__ int    g_starts[C2 + 1];
__device__ int    g_cursor[C2];
__device__ int    g_bsum[512];
__device__ float4 g_pts[NTOT];         // cell-sorted points; .w = local cell id
__device__ ull    g_acc[2];            // fixed-point sums (B2A, A2B)

__device__ __forceinline__ int cellClamp(float v) {
    int c = (int)floorf((v - GRID_LO) * INV_H);
    return min(G - 1, max(0, c));
}

// 1) histogram (counts are zero on entry; k_scan1 re-zeroes them each call)
__global__ void k_count(const float* __restrict__ pred, const float* __restrict__ gt) {
    int i = blockIdx.x * blockDim.x + threadIdx.x;
    if (i == 0) { g_acc[0] = 0ull; g_acc[1] = 0ull; }
    if (i >= NTOT) return;
    int cloud = i >> 14;
    int j = i & (NP - 1);
    const float* p = cloud ? gt : pred;
    float x = p[j * 3 + 0], y = p[j * 3 + 1], z = p[j * 3 + 2];
    int ci = (cellClamp(z) * G + cellClamp(y)) * G + cellClamp(x) + cloud * C1;
    atomicAdd(&g_counts[ci], 1);
}

// 2a) per-block (1024) exclusive scan via warp shuffles; zero counts behind us
__global__ __launch_bounds__(1024) void k_scan1() {
    __shared__ int wsum[32];
    const int i = blockIdx.x * 1024 + threadIdx.x;
    const int lane = threadIdx.x & 31, wid = threadIdx.x >> 5;
    const int v = g_counts[i];
    g_counts[i] = 0;                   // restore invariant for next call
    int s = v;
    #pragma unroll
    for (int off = 1; off < 32; off <<= 1) {
        int n = __shfl_up_sync(0xffffffffu, s, off);
        if (lane >= off) s += n;
    }
    if (lane == 31) wsum[wid] = s;
    __syncthreads();
    if (wid == 0) {
        int ws = wsum[lane];
        #pragma unroll
        for (int off = 1; off < 32; off <<= 1) {
            int n = __shfl_up_sync(0xffffffffu, ws, off);
            if (lane >= off) ws += n;
        }
        wsum[lane] = ws;
    }
    __syncthreads();
    const int bpref = (wid > 0) ? wsum[wid - 1] : 0;
    g_starts[i] = bpref + s - v;       // exclusive within block
    if (threadIdx.x == 1023) g_bsum[blockIdx.x] = bpref + s;
}

// 2b) exclusive scan of the 512 block totals
__global__ void k_scan2() {
    __shared__ int wsum[16];
    const int lane = threadIdx.x & 31, wid = threadIdx.x >> 5;
    const int v = g_bsum[threadIdx.x];
    int s = v;
    #pragma unroll
    for (int off = 1; off < 32; off <<= 1) {
        int n = __shfl_up_sync(0xffffffffu, s, off);
        if (lane >= off) s += n;
    }
    if (lane == 31) wsum[wid] = s;
    __syncthreads();
    if (wid == 0 && lane < 16) {
        int ws = wsum[lane];
        #pragma unroll
        for (int off = 1; off < 16; off <<= 1) {
            int n = __shfl_up_sync(0x0000ffffu, ws, off);
            if (lane >= off) ws += n;
        }
        wsum[lane] = ws;
    }
    __syncthreads();
    const int bpref = (wid > 0) ? wsum[wid - 1] : 0;
    g_bsum[threadIdx.x] = bpref + s - v;
}

// 2c) add block offsets; also materialize the scatter cursor
__global__ __launch_bounds__(1024) void k_scan3() {
    const int i = blockIdx.x * 1024 + threadIdx.x;
    const int v = g_starts[i] + g_bsum[blockIdx.x];
    g_starts[i] = v;
    g_cursor[i] = v;
    if (i == 0) g_starts[C2] = NTOT;
}

// 3) scatter points into cell-contiguous order; cache local cell id in .w
__global__ void k_scatter(const float* __restrict__ pred, const float* __restrict__ gt) {
    int i = blockIdx.x * blockDim.x + threadIdx.x;
    if (i >= NTOT) return;
    int cloud = i >> 14;
    int j = i & (NP - 1);
    const float* p = cloud ? gt : pred;
    float x = p[j * 3 + 0], y = p[j * 3 + 1], z = p[j * 3 + 2];
    int cil = (cellClamp(z) * G + cellClamp(y)) * G + cellClamp(x);
    int pos = atomicAdd(&g_cursor[cil + cloud * C1], 1);
    g_pts[pos] = make_float4(x, y, z, __int_as_float(cil));
}

// 4) exact NN, 2 threads per query, queries in cell-sorted order.
//    Fast path: 3x3x3 rows split 5/4 between the thread pair (batched range
//    loads, indices clamped before load — no speculative OOB), shfl-min
//    merge, box-face stop bound. Rare r>=2 fallback on the even lane.
//    Exact fixed-point (2^40) warp-reduced ull atomics -> deterministic sum.
__global__ __launch_bounds__(256) void k_query() {
    const int t = blockIdx.x * 256 + threadIdx.x;
    const int qi = t >> 1;
    const int half = t & 1;
    const int lane = threadIdx.x & 31;
    const int dir = (qi < NP) ? 0 : 1;       // 0: pred->gt, 1: gt->pred
    const int refbase = dir ? 0 : C1;

    const float4 q = g_pts[qi];
    const float qx = q.x, qy = q.y, qz = q.z;
    const int cil = __float_as_int(q.w);
    const int cx = cil & (G - 1), cy = (cil >> 6) & (G - 1), cz = cil >> 12;

    const int xlo = max(cx - 1, 0), xhi = min(cx + 1, G - 1);

    // ---- ring 0+1 fast path: this thread's 4-5 of the 9 rows ----
    int rs[5], re[5];
    #pragma unroll
    for (int k = 0; k < 5; k++) {
        const int row = 2 * k + half;
        const int z = cz + row / 3 - 1;
        const int y = cy + row % 3 - 1;
        const bool ok = (row < 9) & (z >= 0) & (z < G) & (y >= 0) & (y < G);
        const int rb = ok ? (refbase + (z * G + y) * G) : 0;  // clamped index
        rs[k] = ok ? g_starts[rb + xlo] : 0;
        re[k] = ok ? g_starts[rb + xhi + 1] : 0;
    }

    float best = 1e30f;
    #pragma unroll
    for (int k = 0; k < 5; k++) {
        for (int j = rs[k]; j < re[k]; j++) {
            const float4 p = g_pts[j];
            const float dx = qx - p.x, dy = qy - p.y, dz = qz - p.z;
            best = fminf(best, fmaf(dx, dx, fmaf(dy, dy, dz * dz)));
        }
    }
    best = fminf(best, __shfl_xor_sync(0xffffffffu, best, 1));

    // stop bound at r=1 (grid-clipped sides are fully covered -> +inf)
    float db = 1e30f;
    if (cx - 1 > 0)     db = fminf(db, qx - (GRID_LO + (float)(cx - 1) * H));
    if (cx + 1 < G - 1) db = fminf(db, (GRID_LO + (float)(cx + 2) * H) - qx);
    if (cy - 1 > 0)     db = fminf(db, qy - (GRID_LO + (float)(cy - 1) * H));
    if (cy + 1 < G - 1) db = fminf(db, (GRID_LO + (float)(cy + 2) * H) - qy);
    if (cz - 1 > 0)     db = fminf(db, qz - (GRID_LO + (float)(cz - 1) * H));
    if (cz + 1 < G - 1) db = fminf(db, (GRID_LO + (float)(cz + 2) * H) - qz);

    // ---- rare expanding-ring fallback (even lane only) ----
    if (half == 0 && best > db * db) {
        for (int r = 2; r <= G; r++) {
            const int zlo = max(cz - r, 0), zhi = min(cz + r, G - 1);
            const int ylo = max(cy - r, 0), yhi = min(cy + r, G - 1);
            const int xl  = max(cx - r, 0), xh  = min(cx + r, G - 1);
            for (int z = zlo; z <= zhi; z++) {
                const bool zface = (z == cz - r) || (z == cz + r);
                const int zb = refbase + z * G * G;
                for (int y = ylo; y <= yhi; y++) {
                    const bool face = zface || (y == cy - r) || (y == cy + r);
                    const int yb = zb + y * G;
                    if (face) {
                        const int s = g_starts[yb + xl];
                        const int e = g_starts[yb + xh + 1];
                        for (int j = s; j < e; j++) {
                            const float4 p = g_pts[j];
                            const float dx = qx - p.x, dy = qy - p.y, dz2 = qz - p.z;
                            best = fminf(best, fmaf(dx, dx, fmaf(dy, dy, dz2 * dz2)));
                        }
                    } else {
                        if (cx - r >= 0) {
                            const int ci = yb + cx - r;
                            const int s = g_starts[ci], e = g_starts[ci + 1];
                            for (int j = s; j < e; j++) {
                                const float4 p = g_pts[j];
                                const float dx = qx - p.x, dy = qy - p.y, dz2 = qz - p.z;
                                best = fminf(best, fmaf(dx, dx, fmaf(dy, dy, dz2 * dz2)));
                            }
                        }
                        if (cx + r <= G - 1) {
                            const int ci = yb + cx + r;
                            const int s = g_starts[ci], e = g_starts[ci + 1];
                            for (int j = s; j < e; j++) {
                                const float4 p = g_pts[j];
                                const float dx = qx - p.x, dy = qy - p.y, dz2 = qz - p.z;
                                best = fminf(best, fmaf(dx, dx, fmaf(dy, dy, dz2 * dz2)));
                            }
                        }
                    }
                }
            }
            float db2 = 1e30f;
            if (cx - r > 0)     db2 = fminf(db2, qx - (GRID_LO + (float)(cx - r) * H));
            if (cx + r < G - 1) db2 = fminf(db2, (GRID_LO + (float)(cx + r + 1) * H) - qx);
            if (cy - r > 0)     db2 = fminf(db2, qy - (GRID_LO + (float)(cy - r) * H));
            if (cy + r < G - 1) db2 = fminf(db2, (GRID_LO + (float)(cy + r + 1) * H) - qy);
            if (cz - r > 0)     db2 = fminf(db2, qz - (GRID_LO + (float)(cz - r) * H));
            if (cz + r < G - 1) db2 = fminf(db2, (GRID_LO + (float)(cz + r + 1) * H) - qz);
            if (best <= db2 * db2) break;
        }
    }

    // ---- exact fixed-point accumulation; one contribution per query ----
    ull contrib = (half == 0) ? (ull)((double)best * SCALE) : 0ull;
    #pragma unroll
    for (int off = 16; off > 0; off >>= 1)
        contrib += __shfl_xor_sync(0xffffffffu, contrib, off);
    if (lane == 0) atomicAdd(&g_acc[dir], contrib);   // warp is single-dir (32768 % 32 == 0)
}

// 5) combine
__global__ void k_final(const float* __restrict__ weight, float* __restrict__ out) {
    const double inv = 1.0 / (3.0 * (double)NP * SCALE);
    const double s0 = (double)g_acc[0] * inv;
    const double s1 = (double)g_acc[1] * inv;
    const double w = (double)weight[0];
    out[0] = (float)(w * s0 + (1.0 - w) * s1);
}

extern "C" void kernel_launch(void* const* d_in, const int* in_sizes, int n_in,
                              void* d_out, int out_size) {
    const float* pred   = (const float*)d_in[0];
    const float* gt     = (const float*)d_in[1];
    const float* weight = (const float*)d_in[2];
    float* out = (float*)d_out;
    (void)in_sizes; (void)n_in; (void)out_size;

    k_count<<<(NTOT + 255) / 256, 256>>>(pred, gt);
    k_scan1<<<C2 / 1024, 1024>>>();
    k_scan2<<<1, 512>>>();
    k_scan3<<<C2 / 1024, 1024>>>();
    k_scatter<<<(NTOT + 255) / 256, 256>>>(pred, gt);
    k_query<<<(2 * NTOT) / 256, 256>>>();
    k_final<<<1, 1>>>(weight, out);
}

// round 10
// speedup vs baseline: 3.0309x; 3.0309x over previous
#include <cuda_runtime.h>

#define NP      16384
#define NTOT    (2 * NP)
#define G       32
#define C1      (G * G * G)            // 32768 cells per cloud
#define C2      (2 * C1)               // 65536
#define GRID_LO (-4.8f)
#define H       0.3f
#define INV_H   (1.0f / 0.3f)
#define SCALE   1099511627776.0        // 2^40

typedef unsigned long long ull;

// ---------------- scratch (device globals; zero-initialized at load) -------
__device__ int    g_counts[C2];        // invariant: zero at kernel_launch entry
__device__ int    g_starts[C2 + 1];
__device__ int    g_cursor[C2];
__device__ float4 g_pts[NTOT];         // cell-sorted points; .w = local cell id
__device__ ull    g_acc[2];            // fixed-point sums (B2A, A2B)

__device__ __forceinline__ int cellClamp(float v) {
    int c = (int)floorf((v - GRID_LO) * INV_H);
    return min(G - 1, max(0, c));
}

// 1) histogram (counts are zero on entry; k_scan re-zeroes them each call)
__global__ void k_count(const float* __restrict__ pred, const float* __restrict__ gt) {
    int i = blockIdx.x * blockDim.x + threadIdx.x;
    if (i == 0) { g_acc[0] = 0ull; g_acc[1] = 0ull; }
    if (i >= NTOT) return;
    int cloud = i >> 14;
    int j = i & (NP - 1);
    const float* p = cloud ? gt : pred;
    float x = p[j * 3 + 0], y = p[j * 3 + 1], z = p[j * 3 + 2];
    int ci = (cellClamp(z) * G + cellClamp(y)) * G + cellClamp(x) + cloud * C1;
    atomicAdd(&g_counts[ci], 1);
}

// 2) single-block fused exclusive scan over all C2 cells (64 tiles of 1024).
//    Also zeroes g_counts (restores invariant) and writes the scatter cursor.
__global__ __launch_bounds__(1024) void k_scan() {
    __shared__ int wsum[32];
    const int lane = threadIdx.x & 31, wid = threadIdx.x >> 5;
    int carry = 0;
    for (int tile = 0; tile < C2; tile += 1024) {
        const int i = tile + threadIdx.x;
        const int v = g_counts[i];
        g_counts[i] = 0;
        int s = v;
        #pragma unroll
        for (int off = 1; off < 32; off <<= 1) {
            int n = __shfl_up_sync(0xffffffffu, s, off);
            if (lane >= off) s += n;
        }
        if (lane == 31) wsum[wid] = s;
        __syncthreads();
        if (wid == 0) {
            int ws = wsum[lane];
            #pragma unroll
            for (int off = 1; off < 32; off <<= 1) {
                int n = __shfl_up_sync(0xffffffffu, ws, off);
                if (lane >= off) ws += n;
            }
            wsum[lane] = ws;
        }
        __syncthreads();
        const int bpref = (wid > 0) ? wsum[wid - 1] : 0;
        const int excl = carry + bpref + s - v;
        g_starts[i] = excl;
        g_cursor[i] = excl;
        carry += wsum[31];             // tile total
        __syncthreads();               // protect wsum before next tile
    }
    if (threadIdx.x == 0) g_starts[C2] = NTOT;
}

// 3) scatter points into cell-contiguous order; cache local cell id in .w
__global__ void k_scatter(const float* __restrict__ pred, const float* __restrict__ gt) {
    int i = blockIdx.x * blockDim.x + threadIdx.x;
    if (i >= NTOT) return;
    int cloud = i >> 14;
    int j = i & (NP - 1);
    const float* p = cloud ? gt : pred;
    float x = p[j * 3 + 0], y = p[j * 3 + 1], z = p[j * 3 + 2];
    int cil = (cellClamp(z) * G + cellClamp(y)) * G + cellClamp(x);
    int pos = atomicAdd(&g_cursor[cil + cloud * C1], 1);
    g_pts[pos] = make_float4(x, y, z, __int_as_float(cil));
}

// 4) exact NN, 8 threads per query, queries in cell-sorted order.
//    All intra-group reductions use the 8-LANE GROUP MASK (the fallback is
//    divergent at warp scope but uniform within each 8-lane group — a full
//    warp mask there is UB and was the R6 failure).
__global__ __launch_bounds__(256) void k_query() {
    const int t = blockIdx.x * 256 + threadIdx.x;
    const int qi = t >> 3;
    const int sub = t & 7;
    const int lane = threadIdx.x & 31;
    const unsigned gmask = 0xffu << (lane & 24);   // this thread's 8-lane group
    const int dir = (qi < NP) ? 0 : 1;             // 0: pred->gt, 1: gt->pred
    const int refbase = dir ? 0 : C1;

    const float4 q = g_pts[qi];
    const float qx = q.x, qy = q.y, qz = q.z;
    const int cil = __float_as_int(q.w);
    const int cx = cil & (G - 1), cy = (cil >> 5) & (G - 1), cz = cil >> 10;

    const int xlo = max(cx - 1, 0), xhi = min(cx + 1, G - 1);

    // ---- ring 0+1 fast path: batched loads of the 9 row ranges ----
    int rs[9], re[9];
    #pragma unroll
    for (int row = 0; row < 9; row++) {
        const int z = cz + row / 3 - 1;
        const int y = cy + row % 3 - 1;
        const bool ok = (z >= 0) & (z < G) & (y >= 0) & (y < G);
        const int rb = ok ? (refbase + (z * G + y) * G) : 0;  // clamped index
        rs[row] = ok ? g_starts[rb + xlo] : 0;
        re[row] = ok ? g_starts[rb + xhi + 1] : 0;
    }

    float best = 1e30f;
    #pragma unroll
    for (int row = 0; row < 9; row++) {
        for (int j = rs[row] + sub; j < re[row]; j += 8) {
            const float4 p = g_pts[j];
            const float dx = qx - p.x, dy = qy - p.y, dz = qz - p.z;
            best = fminf(best, fmaf(dx, dx, fmaf(dy, dy, dz * dz)));
        }
    }
    best = fminf(best, __shfl_xor_sync(gmask, best, 1));
    best = fminf(best, __shfl_xor_sync(gmask, best, 2));
    best = fminf(best, __shfl_xor_sync(gmask, best, 4));

    // stop bound at r=1 (grid-clipped sides are fully covered -> +inf)
    float db = 1e30f;
    if (cx - 1 > 0)     db = fminf(db, qx - (GRID_LO + (float)(cx - 1) * H));
    if (cx + 1 < G - 1) db = fminf(db, (GRID_LO + (float)(cx + 2) * H) - qx);
    if (cy - 1 > 0)     db = fminf(db, qy - (GRID_LO + (float)(cy - 1) * H));
    if (cy + 1 < G - 1) db = fminf(db, (GRID_LO + (float)(cy + 2) * H) - qy);
    if (cz - 1 > 0)     db = fminf(db, qz - (GRID_LO + (float)(cz - 1) * H));
    if (cz + 1 < G - 1) db = fminf(db, (GRID_LO + (float)(cz + 2) * H) - qz);

    // ---- rare expanding-ring fallback; uniform within the 8-lane group ----
    if (best > db * db) {
        for (int r = 2; r <= G; r++) {
            const int zlo = max(cz - r, 0), zhi = min(cz + r, G - 1);
            const int ylo = max(cy - r, 0), yhi = min(cy + r, G - 1);
            const int xl  = max(cx - r, 0), xh  = min(cx + r, G - 1);
            for (int z = zlo; z <= zhi; z++) {
                const bool zface = (z == cz - r) || (z == cz + r);
                const int zb = refbase + z * G * G;
                for (int y = ylo; y <= yhi; y++) {
                    const bool face = zface || (y == cy - r) || (y == cy + r);
                    const int yb = zb + y * G;
                    if (face) {
                        const int s = g_starts[yb + xl];
                        const int e = g_starts[yb + xh + 1];
                        for (int j = s + sub; j < e; j += 8) {
                            const float4 p = g_pts[j];
                            const float dx = qx - p.x, dy = qy - p.y, dz2 = qz - p.z;
                            best = fminf(best, fmaf(dx, dx, fmaf(dy, dy, dz2 * dz2)));
                        }
                    } else {
                        if (cx - r >= 0) {
                            const int ci = yb + cx - r;
                            const int s = g_starts[ci], e = g_starts[ci + 1];
                            for (int j = s + sub; j < e; j += 8) {
                                const float4 p = g_pts[j];
                                const float dx = qx - p.x, dy = qy - p.y, dz2 = qz - p.z;
                                best = fminf(best, fmaf(dx, dx, fmaf(dy, dy, dz2 * dz2)));
                            }
                        }
                        if (cx + r <= G - 1) {
                            const int ci = yb + cx + r;
                            const int s = g_starts[ci], e = g_starts[ci + 1];
                            for (int j = s + sub; j < e; j += 8) {
                                const float4 p = g_pts[j];
                                const float dx = qx - p.x, dy = qy - p.y, dz2 = qz - p.z;
                                best = fminf(best, fmaf(dx, dx, fmaf(dy, dy, dz2 * dz2)));
                            }
                        }
                    }
                }
            }
            best = fminf(best, __shfl_xor_sync(gmask, best, 1));
            best = fminf(best, __shfl_xor_sync(gmask, best, 2));
            best = fminf(best, __shfl_xor_sync(gmask, best, 4));
            float db2 = 1e30f;
            if (cx - r > 0)     db2 = fminf(db2, qx - (GRID_LO + (float)(cx - r) * H));
            if (cx + r < G - 1) db2 = fminf(db2, (GRID_LO + (float)(cx + r + 1) * H) - qx);
            if (cy - r > 0)     db2 = fminf(db2, qy - (GRID_LO + (float)(cy - r) * H));
            if (cy + r < G - 1) db2 = fminf(db2, (GRID_LO + (float)(cy + r + 1) * H) - qy);
            if (cz - r > 0)     db2 = fminf(db2, qz - (GRID_LO + (float)(cz - r) * H));
            if (cz + r < G - 1) db2 = fminf(db2, (GRID_LO + (float)(cz + r + 1) * H) - qz);
            if (best <= db2 * db2) break;
        }
    }

    // ---- exact fixed-point accumulation; one contribution per query ----
    // (clamp is pure safety: max possible d^2 over the grid is ~276)
    best = fminf(best, 1e6f);
    ull contrib = (sub == 0) ? (ull)((double)best * SCALE) : 0ull;
    #pragma unroll
    for (int off = 16; off > 0; off >>= 1)
        contrib += __shfl_xor_sync(0xffffffffu, contrib, off);
    if (lane == 0) atomicAdd(&g_acc[dir], contrib);   // warp is single-dir (NP*8 % 32 == 0)
}

// 5) combine
__global__ void k_final(const float* __restrict__ weight, float* __restrict__ out) {
    const double inv = 1.0 / (3.0 * (double)NP * SCALE);
    const double s0 = (double)g_acc[0] * inv;
    const double s1 = (double)g_acc[1] * inv;
    const double w = (double)weight[0];
    out[0] = (float)(w * s0 + (1.0 - w) * s1);
}

extern "C" void kernel_launch(void* const* d_in, const int* in_sizes, int n_in,
                              void* d_out, int out_size) {
    const float* pred   = (const float*)d_in[0];
    const float* gt     = (const float*)d_in[1];
    const float* weight = (const float*)d_in[2];
    float* out = (float*)d_out;
    (void)in_sizes; (void)n_in; (void)out_size;

    k_count<<<NTOT / 256, 256>>>(pred, gt);
    k_scan<<<1, 1024>>>();
    k_scatter<<<NTOT / 256, 256>>>(pred, gt);
    k_query<<<(8 * NTOT) / 256, 256>>>();
    k_final<<<1, 1>>>(weight, out);
}